// round 15
// baseline (speedup 1.0000x reference)
#include <cuda_runtime.h>
#include <cuda_fp16.h>
#include <math.h>
#include <stdint.h>

#define N_NODES 50000
#define E_EDGES 400000
#define FSZ 256
#define H 8
#define D 64
#define HD 512
#define BSZ 1024
#define NH 8
#define DEG 64          // per-slot edge cap (Poisson(8); P(>64) ~ 1e-30)
#define CHUNK 12        // edge rows staged per burst in k_gat

// ---------------- scratch ----------------
__device__ int    g_node_slot[N_NODES];
__device__ int    g_slot_cnt[BSZ];
__device__ int    g_bsrc[BSZ * DEG];
__device__ float  g_WL[H * FSZ];          // [h][f]
__device__ float  g_WR[H * FSZ];          // [h][f]
__device__ float  g_agg[BSZ * H * FSZ];   // softmax-weighted raw-feature sums per (slot, head)
__device__ float  g_x[BSZ * HD];          // post-LN GAT output == [8192][64] rows (b*8+s)
__device__ float  g_MZ[D * 1024];         // [k][ 0..511 = Wq Wk^T/8, 512..1023 = Wv fc_w ]
__device__ __half g_yzh[BSZ * 8 * 1024];  // fp16: per row y | z

// ---------------- f32x2 packed FMA helpers ----------------
__device__ __forceinline__ uint64_t packf2(float x, float y) {
    uint64_t r;
    asm("mov.b64 %0, {%1, %2};" : "=l"(r) : "r"(__float_as_uint(x)), "r"(__float_as_uint(y)));
    return r;
}
__device__ __forceinline__ uint64_t packf2s(float x) { return packf2(x, x); }
__device__ __forceinline__ void ffma2(uint64_t& d, uint64_t a, uint64_t b) {
    asm("fma.rn.f32x2 %0, %1, %2, %0;" : "+l"(d) : "l"(a), "l"(b));
}
__device__ __forceinline__ float2 unpackf2(uint64_t v) {
    uint32_t lo, hi;
    asm("mov.b64 {%0, %1}, %2;" : "=r"(lo), "=r"(hi) : "l"(v));
    return make_float2(__uint_as_float(lo), __uint_as_float(hi));
}

// ---------------- 1. init scratch + fold GAT attn vecs + fold MHA weights ----------------
__global__ void k_initfold(const float* __restrict__ fcw_gat,
                           const float* __restrict__ al,
                           const float* __restrict__ ar,
                           const float* __restrict__ wq, const float* __restrict__ wk,
                           const float* __restrict__ wv, const float* __restrict__ fcw) {
    if (blockIdx.x < 196) {
        int i = blockIdx.x * blockDim.x + threadIdx.x;
        if (i < N_NODES) g_node_slot[i] = 0x7fffffff;
        if (i < BSZ) g_slot_cnt[i] = 0;
        if (i < FSZ * H) {
            int f = i >> 3, h = i & 7;
            float wl = 0.f, wr = 0.f;
            #pragma unroll 8
            for (int d = 0; d < D; d++) {
                float w = fcw_gat[f * HD + h * D + d];
                wl += w * al[h * D + d];
                wr += w * ar[h * D + d];
            }
            g_WL[h * FSZ + f] = wl;
            g_WR[h * FSZ + f] = wr;
        }
        return;
    }
    int fb = blockIdx.x - 196;
    int nh = fb >> 1, which = fb & 1;
    __shared__ float sA[64][68];
    __shared__ float sB[64][68];
    int t = threadIdx.x, tx = t & 15, ty = t >> 4;
    for (int i = t; i < 64 * 64; i += 256) {
        int r = i >> 6, c = i & 63;
        sA[r][c] = which == 0 ? wq[r * HD + nh * 64 + c] : wv[r * HD + nh * 64 + c];
        if (which == 0) sB[c][r] = wk[r * HD + nh * 64 + c];
        else            sB[r][c] = fcw[(nh * 64 + r) * D + c];
    }
    __syncthreads();
    float acc[4][4] = {};
    #pragma unroll 8
    for (int k = 0; k < 64; k++) {
        float a[4], bb[4];
        #pragma unroll
        for (int j = 0; j < 4; j++) a[j] = sA[ty * 4 + j][k];
        #pragma unroll
        for (int i = 0; i < 4; i++) bb[i] = sB[k][tx * 4 + i];
        #pragma unroll
        for (int j = 0; j < 4; j++)
            #pragma unroll
            for (int i = 0; i < 4; i++)
                acc[j][i] += a[j] * bb[i];
    }
    int base = which == 0 ? nh * 64 : 512 + nh * 64;
    float scale = which == 0 ? 0.125f : 1.f;
    #pragma unroll
    for (int j = 0; j < 4; j++)
        #pragma unroll
        for (int i = 0; i < 4; i++)
            g_MZ[(ty * 4 + j) * 1024 + base + tx * 4 + i] = acc[j][i] * scale;
}

// ---------------- 2. mark selected nodes ----------------
__global__ void k_scatter(const int* __restrict__ url) {
    int b = blockIdx.x * blockDim.x + threadIdx.x;
    if (b < BSZ) atomicMin(&g_node_slot[url[b] - 1], b);
}

// ---------------- 3. bucket edges by destination slot ----------------
__global__ void k_filter(const int* __restrict__ src, const int* __restrict__ dst) {
    int base = (blockIdx.x * blockDim.x + threadIdx.x) * 2;
    if (base >= E_EDGES / 4) return;
    int4 dv0 = ((const int4*)dst)[base];
    int4 dv1 = ((const int4*)dst)[base + 1];
    int4 sv0 = ((const int4*)src)[base];
    int4 sv1 = ((const int4*)src)[base + 1];
    int d[8]  = {dv0.x, dv0.y, dv0.z, dv0.w, dv1.x, dv1.y, dv1.z, dv1.w};
    int s8[8] = {sv0.x, sv0.y, sv0.z, sv0.w, sv1.x, sv1.y, sv1.z, sv1.w};
    int sl[8];
    #pragma unroll
    for (int j = 0; j < 8; j++) sl[j] = g_node_slot[d[j]];
    #pragma unroll
    for (int j = 0; j < 8; j++) {
        if (sl[j] != 0x7fffffff) {
            int pos = atomicAdd(&g_slot_cnt[sl[j]], 1);
            if (pos < DEG) g_bsrc[sl[j] * DEG + pos] = s8[j];
        }
    }
}

// ---------------- 4. chunked GAT aggregation, 128-thread CTAs ----------------
// One 128-thread block per slot: thread owns feature cols t and t+128; warp w
// owns heads 2w and 2w+1. 8 CTAs/SM resident -> all 1024 CTAs run in ONE wave.
__global__ __launch_bounds__(128) void k_gat(const float* __restrict__ feat,
                                             const int* __restrict__ url) {
    int b = blockIdx.x, t = threadIdx.x, lane = t & 31, w = t >> 5;   // w in [0,4)
    __shared__ float buf[CHUNK][FSZ];     // 12 KB row buffer
    __shared__ float sdst[FSZ];
    __shared__ float ser[H];
    __shared__ float sscore[CHUNK][H];
    __shared__ float sfact[H];
    __shared__ float swt[CHUNK][H];
    __shared__ int   ssrc[DEG];

    int cnt = g_slot_cnt[b]; if (cnt > DEG) cnt = DEG;
    long nbase = (long)(url[b] - 1) * FSZ;
    sdst[t]       = feat[nbase + t];
    sdst[t + 128] = feat[nbase + t + 128];
    if (t < cnt) ssrc[t] = g_bsrc[b * DEG + t];

    int h0 = 2 * w, h1 = 2 * w + 1;
    float wl0[8], wl1[8];
    #pragma unroll
    for (int j = 0; j < 8; j++) {
        wl0[j] = g_WL[h0 * FSZ + lane + 32 * j];
        wl1[j] = g_WL[h1 * FSZ + lane + 32 * j];
    }
    __syncthreads();

    // er for heads h0, h1 (WR straight from L2, used once)
    {
        float a0 = 0.f, a1 = 0.f;
        #pragma unroll
        for (int j = 0; j < 8; j++) {
            float v = sdst[lane + 32 * j];
            a0 += v * g_WR[h0 * FSZ + lane + 32 * j];
            a1 += v * g_WR[h1 * FSZ + lane + 32 * j];
        }
        #pragma unroll
        for (int o = 16; o; o >>= 1) {
            a0 += __shfl_xor_sync(0xffffffffu, a0, o);
            a1 += __shfl_xor_sync(0xffffffffu, a1, o);
        }
        if (lane == 0) { ser[h0] = a0; ser[h1] = a1; }
    }

    float racc0[H] = {}, racc1[H] = {};
    float my_m = -1e30f, my_s = 0.f;      // owner state, valid for t < 8 (head = t)

    for (int c0 = 0; c0 < cnt; c0 += CHUNK) {
        int ccnt = cnt - c0; if (ccnt > CHUNK) ccnt = CHUNK;
        __syncthreads();                   // buf free from previous chunk
        // burst-load ccnt rows (coalesced, MLP = 2*ccnt per thread-pass)
        for (int i = t; i < ccnt * FSZ; i += 128)
            buf[i >> 8][i & 255] = feat[(long)ssrc[c0 + (i >> 8)] * FSZ + (i & 255)];
        __syncthreads();
        // scores from smem: warp w -> heads h0,h1; fv reused for both heads
        for (int e = 0; e < ccnt; e++) {
            float a0 = 0.f, a1 = 0.f;
            #pragma unroll
            for (int j = 0; j < 8; j++) {
                float fv = buf[e][lane + 32 * j];
                a0 += fv * wl0[j];
                a1 += fv * wl1[j];
            }
            #pragma unroll
            for (int o = 16; o; o >>= 1) {
                a0 += __shfl_xor_sync(0xffffffffu, a0, o);
                a1 += __shfl_xor_sync(0xffffffffu, a1, o);
            }
            if (lane == 0) { sscore[e][h0] = a0; sscore[e][h1] = a1; }
        }
        __syncthreads();
        // chunk-level online softmax bookkeeping (owner thread per head)
        if (t < H) {
            float cm = my_m;
            for (int e = 0; e < ccnt; e++) {
                float sc = sscore[e][t] + ser[t];
                sc = sc > 0.f ? sc : 0.2f * sc;
                cm = fmaxf(cm, sc);
            }
            float fct = __expf(my_m - cm);
            float sa = 0.f;
            for (int e = 0; e < ccnt; e++) {
                float sc = sscore[e][t] + ser[t];
                sc = sc > 0.f ? sc : 0.2f * sc;
                float we = __expf(sc - cm);
                swt[e][t] = we;
                sa += we;
            }
            my_s = my_s * fct + sa;
            my_m = cm;
            sfact[t] = fct;
        }
        __syncthreads();
        // aggregation burst: thread owns feature cols t and t+128
        #pragma unroll
        for (int h = 0; h < H; h++) { racc0[h] *= sfact[h]; racc1[h] *= sfact[h]; }
        for (int e = 0; e < ccnt; e++) {
            float f0 = buf[e][t];
            float f1 = buf[e][t + 128];
            #pragma unroll
            for (int h = 0; h < H; h++) {
                float ww = swt[e][h];
                racc0[h] += ww * f0;
                racc1[h] += ww * f1;
            }
        }
    }
    if (t < H) sfact[t] = 1.f / fmaxf(my_s, 1e-20f);
    __syncthreads();
    #pragma unroll
    for (int h = 0; h < H; h++) {
        float inv = sfact[h];
        g_agg[(b * H + h) * FSZ + t]       = racc0[h] * inv;
        g_agg[(b * H + h) * FSZ + t + 128] = racc1[h] * inv;
    }
}

// ---------------- 5. fused dual GEMM (res + agg@W) + bias + LayerNorm (FFMA2) ----------------
__global__ void k_rst_res(const float* __restrict__ feat, const float* __restrict__ resw,
                          const float* __restrict__ fcw, const int* __restrict__ url,
                          const float* __restrict__ bias,
                          const float* __restrict__ lg, const float* __restrict__ lb) {
    __shared__ float sF[32][72];
    __shared__ float sG[32][72];
    __shared__ float sBr[32][68];
    __shared__ float sBw[32][68];
    __shared__ int snode[64], sslot[64];
    int r0 = blockIdx.y * 64, hcol = blockIdx.x, c0 = hcol * 64;
    int t = threadIdx.x, tx = t & 15, ty = t >> 4;
    if (t < 64) {
        int n = url[r0 + t] - 1;
        snode[t] = n;
        sslot[t] = g_node_slot[n];
    }
    __syncthreads();
    uint64_t acc2[4][2] = {};
    for (int k0 = 0; k0 < FSZ; k0 += 32) {
        for (int i = t; i < 64 * 32; i += 256) {
            int k = i & 31, r = i >> 5;
            sF[k][r] = feat[(long)snode[r] * FSZ + k0 + k];
            sG[k][r] = g_agg[(sslot[r] * H + hcol) * FSZ + k0 + k];
        }
        for (int i = t; i < 32 * 64; i += 256) {
            int k = i >> 6, c = i & 63;
            sBr[k][c] = resw[(k0 + k) * HD + c0 + c];
            sBw[k][c] = fcw[(k0 + k) * HD + c0 + c];
        }
        __syncthreads();
        #pragma unroll 4
        for (int kk = 0; kk < 32; kk++) {
            float4 af = *(const float4*)&sF[kk][ty * 4];
            float4 ag = *(const float4*)&sG[kk][ty * 4];
            float4 brv = *(const float4*)&sBr[kk][tx * 4];
            float4 bwv = *(const float4*)&sBw[kk][tx * 4];
            uint64_t br2[2] = { packf2(brv.x, brv.y), packf2(brv.z, brv.w) };
            uint64_t bw2[2] = { packf2(bwv.x, bwv.y), packf2(bwv.z, bwv.w) };
            float afv[4] = {af.x, af.y, af.z, af.w};
            float agv[4] = {ag.x, ag.y, ag.z, ag.w};
            #pragma unroll
            for (int j = 0; j < 4; j++) {
                uint64_t a2 = packf2s(afv[j]);
                uint64_t g2 = packf2s(agv[j]);
                ffma2(acc2[j][0], a2, br2[0]);
                ffma2(acc2[j][1], a2, br2[1]);
                ffma2(acc2[j][0], g2, bw2[0]);
                ffma2(acc2[j][1], g2, bw2[1]);
            }
        }
        __syncthreads();
    }
    #pragma unroll
    for (int j = 0; j < 4; j++) {
        float2 lo = unpackf2(acc2[j][0]), hi = unpackf2(acc2[j][1]);
        float acc[4] = {lo.x, lo.y, hi.x, hi.y};
        float s = 0.f, ss = 0.f;
        #pragma unroll
        for (int i = 0; i < 4; i++) {
            acc[i] += bias[c0 + tx * 4 + i];
            s += acc[i]; ss += acc[i] * acc[i];
        }
        #pragma unroll
        for (int o = 1; o < 16; o <<= 1) {
            s  += __shfl_xor_sync(0xffffffffu, s, o);
            ss += __shfl_xor_sync(0xffffffffu, ss, o);
        }
        float mu = s * (1.f / D), var = ss * (1.f / D) - mu * mu;
        float rs = rsqrtf(var + 1e-6f);
        #pragma unroll
        for (int i = 0; i < 4; i++) {
            int c = tx * 4 + i;
            g_x[(r0 + ty * 4 + j) * HD + c0 + c] = (acc[i] - mu) * rs * lg[c] + lb[c];
        }
    }
}

// ---------------- 6. yz GEMM: [8192,64] x [64,1024] (FFMA2, fp16 output) ----------------
__global__ void k_yz() {
    __shared__ float sA[64][72];
    __shared__ float sB[64][68];
    int r0 = blockIdx.y * 64, c0 = blockIdx.x * 64;
    int t = threadIdx.x, tx = t & 15, ty = t >> 4;
    for (int i = t; i < 64 * 64; i += 256) {
        int k = i & 63, r = i >> 6;
        sA[k][r] = g_x[(r0 + r) * D + k];
    }
    for (int i = t; i < 64 * 64; i += 256) {
        int k = i >> 6, c = i & 63;
        sB[k][c] = g_MZ[k * 1024 + c0 + c];
    }
    __syncthreads();
    uint64_t acc2[4][2] = {};
    #pragma unroll 8
    for (int k = 0; k < 64; k++) {
        float4 a4 = *(const float4*)&sA[k][ty * 4];
        float4 b4 = *(const float4*)&sB[k][tx * 4];
        uint64_t b2[2] = { packf2(b4.x, b4.y), packf2(b4.z, b4.w) };
        float av[4] = {a4.x, a4.y, a4.z, a4.w};
        #pragma unroll
        for (int j = 0; j < 4; j++) {
            uint64_t aj = packf2s(av[j]);
            ffma2(acc2[j][0], aj, b2[0]);
            ffma2(acc2[j][1], aj, b2[1]);
        }
    }
    #pragma unroll
    for (int j = 0; j < 4; j++) {
        float2 lo = unpackf2(acc2[j][0]), hi = unpackf2(acc2[j][1]);
        __half2 h0 = __floats2half2_rn(lo.x, lo.y);
        __half2 h1 = __floats2half2_rn(hi.x, hi.y);
        uint2 p;
        p.x = *(uint32_t*)&h0;
        p.y = *(uint32_t*)&h1;
        *(uint2*)&g_yzh[(long)(r0 + ty * 4 + j) * 1024 + c0 + tx * 4] = p;
    }
}

// ---------------- 7. fused per-b epilogue (fp16 yz input) ----------------
__global__ void k_attn_final(const float* __restrict__ fcb,
                             const float* __restrict__ mlg, const float* __restrict__ mlb,
                             const float* __restrict__ ow,  const float* __restrict__ ob,
                             float* __restrict__ out) {
    int b = blockIdx.x, t = threadIdx.x, lane = t & 31, w = t >> 5;   // w = nh
    __shared__ float sx[8][68];
    __shared__ float sy[8][8][68];
    __shared__ float sat[NH][8][9];
    __shared__ float sout[NH][8][72];
    __shared__ float sred[8][68];
    __shared__ float spool[64];
    const float*  xb = g_x + (long)b * HD;
    const __half* yz = g_yzh + (long)b * 8 * 1024;
    for (int i = t; i < 128; i += 256) {
        int r = i >> 4, c4 = (i & 15) * 4;
        *(float4*)&sx[r][c4] = *(const float4*)&xb[r * 64 + c4];
    }
    for (int j = lane; j < 128; j += 32) {
        int r = j >> 4, c4 = (j & 15) * 4;
        uint2 p = *(const uint2*)&yz[r * 1024 + w * 64 + c4];
        float2 f0 = __half22float2(*(__half2*)&p.x);
        float2 f1 = __half22float2(*(__half2*)&p.y);
        sy[w][r][c4]     = f0.x; sy[w][r][c4 + 1] = f0.y;
        sy[w][r][c4 + 2] = f1.x; sy[w][r][c4 + 3] = f1.y;
    }
    __syncthreads();
    #pragma unroll
    for (int pp = 0; pp < 2; pp++) {
        int p = lane + pp * 32, qi = p >> 3, ki = p & 7;
        float a = 0.f;
        #pragma unroll
        for (int d = 0; d < 64; d++) a += sy[w][qi][d] * sx[ki][d];
        sat[w][qi][ki] = a;
    }
    __syncwarp();
    if (lane < 8) {
        float mx = -1e30f;
        #pragma unroll
        for (int k2 = 0; k2 < 8; k2++) mx = fmaxf(mx, sat[w][lane][k2]);
        float s = 0.f;
        #pragma unroll
        for (int k2 = 0; k2 < 8; k2++) { float e = __expf(sat[w][lane][k2] - mx); s += e; sat[w][lane][k2] = e; }
        float inv = 1.f / s;
        #pragma unroll
        for (int k2 = 0; k2 < 8; k2++) sat[w][lane][k2] *= inv;
    }
    __syncwarp();
    #pragma unroll
    for (int pp = 0; pp < 2; pp++) {
        int d = lane + pp * 32;
        float vk[8];
        #pragma unroll
        for (int k2 = 0; k2 < 8; k2++) vk[k2] = __half2float(yz[k2 * 1024 + 512 + w * 64 + d]);
        #pragma unroll
        for (int qi = 0; qi < 8; qi++) {
            float a = 0.f;
            #pragma unroll
            for (int k2 = 0; k2 < 8; k2++) a += sat[w][qi][k2] * vk[k2];
            sout[w][qi][d] = a;
        }
    }
    __syncthreads();
    for (int i = t; i < 512; i += 256) {
        int qi = i >> 6, d = i & 63;
        float r = sx[qi][d] + fcb[d];
        #pragma unroll
        for (int w2 = 0; w2 < NH; w2++) r += sout[w2][qi][d];
        sred[qi][d] = r;
    }
    __syncthreads();
    {
        float v0 = sred[w][lane], v1 = sred[w][lane + 32];
        float s = v0 + v1, ss = v0 * v0 + v1 * v1;
        #pragma unroll
        for (int o = 16; o; o >>= 1) {
            s  += __shfl_xor_sync(0xffffffffu, s, o);
            ss += __shfl_xor_sync(0xffffffffu, ss, o);
        }
        float mu = s * (1.f / D), var = ss * (1.f / D) - mu * mu;
        float rs = rsqrtf(var + 1e-6f);
        sred[w][lane]      = (v0 - mu) * rs * mlg[lane] + mlb[lane];
        sred[w][lane + 32] = (v1 - mu) * rs * mlg[lane + 32] + mlb[lane + 32];
    }
    __syncthreads();
    if (t < 64) {
        float p = 0.f;
        #pragma unroll
        for (int s2 = 0; s2 < 8; s2++) p += sred[s2][t];
        spool[t] = p;
    }
    __syncthreads();
    if (t < 2) {
        float a = ob[t];
        #pragma unroll 8
        for (int d = 0; d < D; d++) a += spool[d] * ow[d * 2 + t];
        out[b * 2 + t] = a;
    }
}

// ---------------- launch ----------------
extern "C" void kernel_launch(void* const* d_in, const int* in_sizes, int n_in,
                              void* d_out, int out_size) {
    const float* features  = (const float*)d_in[0];
    const int*   src       = (const int*)  d_in[1];
    const int*   dst       = (const int*)  d_in[2];
    const int*   url       = (const int*)  d_in[3];
    const float* gat_fc_w  = (const float*)d_in[4];
    const float* attn_l    = (const float*)d_in[5];
    const float* attn_r    = (const float*)d_in[6];
    const float* gat_res_w = (const float*)d_in[7];
    const float* gat_bias  = (const float*)d_in[8];
    const float* ln_g      = (const float*)d_in[9];
    const float* ln_b      = (const float*)d_in[10];
    const float* wq        = (const float*)d_in[11];
    const float* wk        = (const float*)d_in[12];
    const float* wv        = (const float*)d_in[13];
    const float* fc_w      = (const float*)d_in[14];
    const float* fc_b      = (const float*)d_in[15];
    const float* mha_ln_g  = (const float*)d_in[16];
    const float* mha_ln_b  = (const float*)d_in[17];
    const float* out_w     = (const float*)d_in[18];
    const float* out_b     = (const float*)d_in[19];
    float* out = (float*)d_out;

    k_initfold<<<212, 256>>>(gat_fc_w, attn_l, attn_r, wq, wk, wv, fc_w);
    k_scatter<<<4, 256>>>(url);
    k_filter<<<196, 256>>>(src, dst);
    k_gat<<<BSZ, 128>>>(features, url);
    k_rst_res<<<dim3(8, BSZ / 64), 256>>>(features, gat_res_w, gat_fc_w, url,
                                          gat_bias, ln_g, ln_b);
    k_yz<<<dim3(16, 128), 256>>>();
    k_attn_final<<<BSZ, 256>>>(fc_b, mha_ln_g, mha_ln_b, out_w, out_b, out);
}

// round 16
// speedup vs baseline: 1.0959x; 1.0959x over previous
#include <cuda_runtime.h>
#include <cuda_fp16.h>
#include <math.h>
#include <stdint.h>

#define N_NODES 50000
#define E_EDGES 400000
#define FSZ 256
#define H 8
#define D 64
#define HD 512
#define BSZ 1024
#define NH 8
#define DEG 64          // per-slot edge cap (Poisson(8); P(>64) ~ 1e-30)
#define CHUNK 16        // edge rows staged per burst in k_gat

// ---------------- scratch ----------------
__device__ int    g_node_slot[N_NODES];
__device__ int    g_slot_cnt[BSZ];
__device__ int    g_bsrc[BSZ * DEG];
__device__ float  g_WL[H * FSZ];          // [h][f]
__device__ float  g_WR[H * FSZ];          // [h][f]
__device__ float  g_agg[BSZ * H * FSZ];   // softmax-weighted raw-feature sums per (slot, head)
__device__ float  g_x[BSZ * HD];          // post-LN GAT output == [8192][64] rows (b*8+s)
__device__ float  g_MZ[D * 1024];         // [k][ 0..511 = Wq Wk^T/8, 512..1023 = Wv fc_w ]
__device__ __half g_yzh[BSZ * 8 * 1024];  // fp16: per row y | z

// ---------------- f32x2 packed FMA helpers ----------------
__device__ __forceinline__ uint64_t packf2(float x, float y) {
    uint64_t r;
    asm("mov.b64 %0, {%1, %2};" : "=l"(r) : "r"(__float_as_uint(x)), "r"(__float_as_uint(y)));
    return r;
}
__device__ __forceinline__ uint64_t packf2s(float x) { return packf2(x, x); }
__device__ __forceinline__ void ffma2(uint64_t& d, uint64_t a, uint64_t b) {
    asm("fma.rn.f32x2 %0, %1, %2, %0;" : "+l"(d) : "l"(a), "l"(b));
}
__device__ __forceinline__ float2 unpackf2(uint64_t v) {
    uint32_t lo, hi;
    asm("mov.b64 {%0, %1}, %2;" : "=r"(lo), "=r"(hi) : "l"(v));
    return make_float2(__uint_as_float(lo), __uint_as_float(hi));
}

// ---------------- 1. init scratch + fold GAT attn vecs + fold MHA weights ----------------
__global__ void k_initfold(const float* __restrict__ fcw_gat,
                           const float* __restrict__ al,
                           const float* __restrict__ ar,
                           const float* __restrict__ wq, const float* __restrict__ wk,
                           const float* __restrict__ wv, const float* __restrict__ fcw) {
    if (blockIdx.x < 196) {
        int i = blockIdx.x * blockDim.x + threadIdx.x;
        if (i < N_NODES) g_node_slot[i] = 0x7fffffff;
        if (i < BSZ) g_slot_cnt[i] = 0;
        if (i < FSZ * H) {
            int f = i >> 3, h = i & 7;
            float wl = 0.f, wr = 0.f;
            #pragma unroll 8
            for (int d = 0; d < D; d++) {
                float w = fcw_gat[f * HD + h * D + d];
                wl += w * al[h * D + d];
                wr += w * ar[h * D + d];
            }
            g_WL[h * FSZ + f] = wl;
            g_WR[h * FSZ + f] = wr;
        }
        return;
    }
    int fb = blockIdx.x - 196;
    int nh = fb >> 1, which = fb & 1;
    __shared__ float sA[64][68];
    __shared__ float sB[64][68];
    int t = threadIdx.x, tx = t & 15, ty = t >> 4;
    for (int i = t; i < 64 * 64; i += 256) {
        int r = i >> 6, c = i & 63;
        sA[r][c] = which == 0 ? wq[r * HD + nh * 64 + c] : wv[r * HD + nh * 64 + c];
        if (which == 0) sB[c][r] = wk[r * HD + nh * 64 + c];
        else            sB[r][c] = fcw[(nh * 64 + r) * D + c];
    }
    __syncthreads();
    float acc[4][4] = {};
    #pragma unroll 8
    for (int k = 0; k < 64; k++) {
        float a[4], bb[4];
        #pragma unroll
        for (int j = 0; j < 4; j++) a[j] = sA[ty * 4 + j][k];
        #pragma unroll
        for (int i = 0; i < 4; i++) bb[i] = sB[k][tx * 4 + i];
        #pragma unroll
        for (int j = 0; j < 4; j++)
            #pragma unroll
            for (int i = 0; i < 4; i++)
                acc[j][i] += a[j] * bb[i];
    }
    int base = which == 0 ? nh * 64 : 512 + nh * 64;
    float scale = which == 0 ? 0.125f : 1.f;
    #pragma unroll
    for (int j = 0; j < 4; j++)
        #pragma unroll
        for (int i = 0; i < 4; i++)
            g_MZ[(ty * 4 + j) * 1024 + base + tx * 4 + i] = acc[j][i] * scale;
}

// ---------------- 2. mark selected nodes ----------------
__global__ void k_scatter(const int* __restrict__ url) {
    int b = blockIdx.x * blockDim.x + threadIdx.x;
    if (b < BSZ) atomicMin(&g_node_slot[url[b] - 1], b);
}

// ---------------- 3. bucket edges by destination slot (4 edges/thread) ----------------
__global__ void k_filter(const int* __restrict__ src, const int* __restrict__ dst) {
    int i4 = blockIdx.x * blockDim.x + threadIdx.x;
    if (i4 >= E_EDGES / 4) return;
    int4 dv = ((const int4*)dst)[i4];
    int4 sv = ((const int4*)src)[i4];
    int d[4]  = {dv.x, dv.y, dv.z, dv.w};
    int s4[4] = {sv.x, sv.y, sv.z, sv.w};
    int sl[4];
    #pragma unroll
    for (int j = 0; j < 4; j++) sl[j] = g_node_slot[d[j]];
    #pragma unroll
    for (int j = 0; j < 4; j++) {
        if (sl[j] != 0x7fffffff) {
            int pos = atomicAdd(&g_slot_cnt[sl[j]], 1);
            if (pos < DEG) g_bsrc[sl[j] * DEG + pos] = s4[j];
        }
    }
}

// ---------------- 4. chunked single-pass GAT aggregation (R14 form) ----------------
__global__ __launch_bounds__(256) void k_gat(const float* __restrict__ feat,
                                             const int* __restrict__ url) {
    int b = blockIdx.x, t = threadIdx.x, lane = t & 31, w = t >> 5;   // w = head
    __shared__ float buf[CHUNK][FSZ];     // 16 KB row buffer
    __shared__ float sdst[FSZ];
    __shared__ float ser[H];
    __shared__ float sscore[CHUNK][H];
    __shared__ float sfact[H];
    __shared__ float swt[CHUNK][H];
    __shared__ int   ssrc[DEG];

    int cnt = g_slot_cnt[b]; if (cnt > DEG) cnt = DEG;
    sdst[t] = feat[(long)(url[b] - 1) * FSZ + t];
    if (t < cnt) ssrc[t] = g_bsrc[b * DEG + t];

    float wl[8];
    #pragma unroll
    for (int j = 0; j < 8; j++) wl[j] = g_WL[w * FSZ + lane + 32 * j];
    __syncthreads();

    {
        float a = 0.f;
        #pragma unroll
        for (int j = 0; j < 8; j++) a += sdst[lane + 32 * j] * g_WR[w * FSZ + lane + 32 * j];
        #pragma unroll
        for (int o = 16; o; o >>= 1) a += __shfl_xor_sync(0xffffffffu, a, o);
        if (lane == 0) ser[w] = a;
    }

    float racc[H] = {};
    float my_m = -1e30f, my_s = 0.f;

    for (int c0 = 0; c0 < cnt; c0 += CHUNK) {
        int ccnt = cnt - c0; if (ccnt > CHUNK) ccnt = CHUNK;
        __syncthreads();
        for (int i = t; i < ccnt * FSZ; i += 256)
            buf[i >> 8][i & 255] = feat[(long)ssrc[c0 + (i >> 8)] * FSZ + (i & 255)];
        __syncthreads();
        for (int e = 0; e < ccnt; e += 2) {
            float a0 = 0.f, a1 = 0.f;
            #pragma unroll
            for (int j = 0; j < 8; j++) a0 += buf[e][lane + 32 * j] * wl[j];
            if (e + 1 < ccnt) {
                #pragma unroll
                for (int j = 0; j < 8; j++) a1 += buf[e + 1][lane + 32 * j] * wl[j];
            }
            #pragma unroll
            for (int o = 16; o; o >>= 1) {
                a0 += __shfl_xor_sync(0xffffffffu, a0, o);
                a1 += __shfl_xor_sync(0xffffffffu, a1, o);
            }
            if (lane == 0) {
                sscore[e][w] = a0;
                if (e + 1 < ccnt) sscore[e + 1][w] = a1;
            }
        }
        __syncthreads();
        if (t < H) {
            float cm = my_m;
            for (int e = 0; e < ccnt; e++) {
                float sc = sscore[e][t] + ser[t];
                sc = sc > 0.f ? sc : 0.2f * sc;
                cm = fmaxf(cm, sc);
            }
            float fct = __expf(my_m - cm);
            float sa = 0.f;
            for (int e = 0; e < ccnt; e++) {
                float sc = sscore[e][t] + ser[t];
                sc = sc > 0.f ? sc : 0.2f * sc;
                float we = __expf(sc - cm);
                swt[e][t] = we;
                sa += we;
            }
            my_s = my_s * fct + sa;
            my_m = cm;
            sfact[t] = fct;
        }
        __syncthreads();
        #pragma unroll
        for (int h = 0; h < H; h++) racc[h] *= sfact[h];
        for (int e = 0; e < ccnt; e++) {
            float fv = buf[e][t];
            #pragma unroll
            for (int h = 0; h < H; h++) racc[h] += swt[e][h] * fv;
        }
    }
    if (t < H) sfact[t] = 1.f / fmaxf(my_s, 1e-20f);
    __syncthreads();
    #pragma unroll
    for (int h = 0; h < H; h++)
        g_agg[(b * H + h) * FSZ + t] = racc[h] * sfact[h];
}

// ---------------- 5. fused dual GEMM + bias + LayerNorm (FFMA2, 32-row tiles, 256 CTAs) ----------------
__global__ void k_rst_res(const float* __restrict__ feat, const float* __restrict__ resw,
                          const float* __restrict__ fcw, const int* __restrict__ url,
                          const float* __restrict__ bias,
                          const float* __restrict__ lg, const float* __restrict__ lb) {
    __shared__ float sF[32][36];     // [k][r] transposed, 32 rows
    __shared__ float sG[32][36];
    __shared__ float sBr[32][68];
    __shared__ float sBw[32][68];
    __shared__ int snode[32], sslot[32];
    int r0 = blockIdx.y * 32, hcol = blockIdx.x, c0 = hcol * 64;
    int t = threadIdx.x, tx = t & 15, ty = t >> 4;   // ty 0..15 -> 2 rows each
    if (t < 32) {
        int n = url[r0 + t] - 1;
        snode[t] = n;
        sslot[t] = g_node_slot[n];
    }
    __syncthreads();
    uint64_t acc2[2][2] = {};
    for (int k0 = 0; k0 < FSZ; k0 += 32) {
        for (int i = t; i < 32 * 32; i += 256) {
            int k = i & 31, r = i >> 5;
            sF[k][r] = feat[(long)snode[r] * FSZ + k0 + k];
            sG[k][r] = g_agg[(sslot[r] * H + hcol) * FSZ + k0 + k];
        }
        for (int i = t; i < 32 * 64; i += 256) {
            int k = i >> 6, c = i & 63;
            sBr[k][c] = resw[(k0 + k) * HD + c0 + c];
            sBw[k][c] = fcw[(k0 + k) * HD + c0 + c];
        }
        __syncthreads();
        #pragma unroll 4
        for (int kk = 0; kk < 32; kk++) {
            float2 af = *(const float2*)&sF[kk][ty * 2];
            float2 ag = *(const float2*)&sG[kk][ty * 2];
            float4 brv = *(const float4*)&sBr[kk][tx * 4];
            float4 bwv = *(const float4*)&sBw[kk][tx * 4];
            uint64_t br2[2] = { packf2(brv.x, brv.y), packf2(brv.z, brv.w) };
            uint64_t bw2[2] = { packf2(bwv.x, bwv.y), packf2(bwv.z, bwv.w) };
            float afv[2] = {af.x, af.y};
            float agv[2] = {ag.x, ag.y};
            #pragma unroll
            for (int j = 0; j < 2; j++) {
                uint64_t a2 = packf2s(afv[j]);
                uint64_t g2 = packf2s(agv[j]);
                ffma2(acc2[j][0], a2, br2[0]);
                ffma2(acc2[j][1], a2, br2[1]);
                ffma2(acc2[j][0], g2, bw2[0]);
                ffma2(acc2[j][1], g2, bw2[1]);
            }
        }
        __syncthreads();
    }
    #pragma unroll
    for (int j = 0; j < 2; j++) {
        float2 lo = unpackf2(acc2[j][0]), hi = unpackf2(acc2[j][1]);
        float acc[4] = {lo.x, lo.y, hi.x, hi.y};
        float s = 0.f, ss = 0.f;
        #pragma unroll
        for (int i = 0; i < 4; i++) {
            acc[i] += bias[c0 + tx * 4 + i];
            s += acc[i]; ss += acc[i] * acc[i];
        }
        #pragma unroll
        for (int o = 1; o < 16; o <<= 1) {
            s  += __shfl_xor_sync(0xffffffffu, s, o);
            ss += __shfl_xor_sync(0xffffffffu, ss, o);
        }
        float mu = s * (1.f / D), var = ss * (1.f / D) - mu * mu;
        float rs = rsqrtf(var + 1e-6f);
        #pragma unroll
        for (int i = 0; i < 4; i++) {
            int c = tx * 4 + i;
            g_x[(r0 + ty * 2 + j) * HD + c0 + c] = (acc[i] - mu) * rs * lg[c] + lb[c];
        }
    }
}

// ---------------- 6. yz GEMM: [8192,64] x [64,1024] (FFMA2, fp16 output) ----------------
__global__ void k_yz() {
    __shared__ float sA[64][72];
    __shared__ float sB[64][68];
    int r0 = blockIdx.y * 64, c0 = blockIdx.x * 64;
    int t = threadIdx.x, tx = t & 15, ty = t >> 4;
    for (int i = t; i < 64 * 64; i += 256) {
        int k = i & 63, r = i >> 6;
        sA[k][r] = g_x[(r0 + r) * D + k];
    }
    for (int i = t; i < 64 * 64; i += 256) {
        int k = i >> 6, c = i & 63;
        sB[k][c] = g_MZ[k * 1024 + c0 + c];
    }
    __syncthreads();
    uint64_t acc2[4][2] = {};
    #pragma unroll 8
    for (int k = 0; k < 64; k++) {
        float4 a4 = *(const float4*)&sA[k][ty * 4];
        float4 b4 = *(const float4*)&sB[k][tx * 4];
        uint64_t b2[2] = { packf2(b4.x, b4.y), packf2(b4.z, b4.w) };
        float av[4] = {a4.x, a4.y, a4.z, a4.w};
        #pragma unroll
        for (int j = 0; j < 4; j++) {
            uint64_t aj = packf2s(av[j]);
            ffma2(acc2[j][0], aj, b2[0]);
            ffma2(acc2[j][1], aj, b2[1]);
        }
    }
    #pragma unroll
    for (int j = 0; j < 4; j++) {
        float2 lo = unpackf2(acc2[j][0]), hi = unpackf2(acc2[j][1]);
        __half2 h0 = __floats2half2_rn(lo.x, lo.y);
        __half2 h1 = __floats2half2_rn(hi.x, hi.y);
        uint2 p;
        p.x = *(uint32_t*)&h0;
        p.y = *(uint32_t*)&h1;
        *(uint2*)&g_yzh[(long)(r0 + ty * 4 + j) * 1024 + c0 + tx * 4] = p;
    }
}

// ---------------- 7. fused per-b epilogue (fp16 yz input) ----------------
__global__ void k_attn_final(const float* __restrict__ fcb,
                             const float* __restrict__ mlg, const float* __restrict__ mlb,
                             const float* __restrict__ ow,  const float* __restrict__ ob,
                             float* __restrict__ out) {
    int b = blockIdx.x, t = threadIdx.x, lane = t & 31, w = t >> 5;   // w = nh
    __shared__ float sx[8][68];
    __shared__ float sy[8][8][68];
    __shared__ float sat[NH][8][9];
    __shared__ float sout[NH][8][72];
    __shared__ float sred[8][68];
    __shared__ float spool[64];
    const float*  xb = g_x + (long)b * HD;
    const __half* yz = g_yzh + (long)b * 8 * 1024;
    for (int i = t; i < 128; i += 256) {
        int r = i >> 4, c4 = (i & 15) * 4;
        *(float4*)&sx[r][c4] = *(const float4*)&xb[r * 64 + c4];
    }
    for (int j = lane; j < 128; j += 32) {
        int r = j >> 4, c4 = (j & 15) * 4;
        uint2 p = *(const uint2*)&yz[r * 1024 + w * 64 + c4];
        float2 f0 = __half22float2(*(__half2*)&p.x);
        float2 f1 = __half22float2(*(__half2*)&p.y);
        sy[w][r][c4]     = f0.x; sy[w][r][c4 + 1] = f0.y;
        sy[w][r][c4 + 2] = f1.x; sy[w][r][c4 + 3] = f1.y;
    }
    __syncthreads();
    #pragma unroll
    for (int pp = 0; pp < 2; pp++) {
        int p = lane + pp * 32, qi = p >> 3, ki = p & 7;
        float a = 0.f;
        #pragma unroll
        for (int d = 0; d < 64; d++) a += sy[w][qi][d] * sx[ki][d];
        sat[w][qi][ki] = a;
    }
    __syncwarp();
    if (lane < 8) {
        float mx = -1e30f;
        #pragma unroll
        for (int k2 = 0; k2 < 8; k2++) mx = fmaxf(mx, sat[w][lane][k2]);
        float s = 0.f;
        #pragma unroll
        for (int k2 = 0; k2 < 8; k2++) { float e = __expf(sat[w][lane][k2] - mx); s += e; sat[w][lane][k2] = e; }
        float inv = 1.f / s;
        #pragma unroll
        for (int k2 = 0; k2 < 8; k2++) sat[w][lane][k2] *= inv;
    }
    __syncwarp();
    #pragma unroll
    for (int pp = 0; pp < 2; pp++) {
        int d = lane + pp * 32;
        float vk[8];
        #pragma unroll
        for (int k2 = 0; k2 < 8; k2++) vk[k2] = __half2float(yz[k2 * 1024 + 512 + w * 64 + d]);
        #pragma unroll
        for (int qi = 0; qi < 8; qi++) {
            float a = 0.f;
            #pragma unroll
            for (int k2 = 0; k2 < 8; k2++) a += sat[w][qi][k2] * vk[k2];
            sout[w][qi][d] = a;
        }
    }
    __syncthreads();
    for (int i = t; i < 512; i += 256) {
        int qi = i >> 6, d = i & 63;
        float r = sx[qi][d] + fcb[d];
        #pragma unroll
        for (int w2 = 0; w2 < NH; w2++) r += sout[w2][qi][d];
        sred[qi][d] = r;
    }
    __syncthreads();
    {
        float v0 = sred[w][lane], v1 = sred[w][lane + 32];
        float s = v0 + v1, ss = v0 * v0 + v1 * v1;
        #pragma unroll
        for (int o = 16; o; o >>= 1) {
            s  += __shfl_xor_sync(0xffffffffu, s, o);
            ss += __shfl_xor_sync(0xffffffffu, ss, o);
        }
        float mu = s * (1.f / D), var = ss * (1.f / D) - mu * mu;
        float rs = rsqrtf(var + 1e-6f);
        sred[w][lane]      = (v0 - mu) * rs * mlg[lane] + mlb[lane];
        sred[w][lane + 32] = (v1 - mu) * rs * mlg[lane + 32] + mlb[lane + 32];
    }
    __syncthreads();
    if (t < 64) {
        float p = 0.f;
        #pragma unroll
        for (int s2 = 0; s2 < 8; s2++) p += sred[s2][t];
        spool[t] = p;
    }
    __syncthreads();
    if (t < 2) {
        float a = ob[t];
        #pragma unroll 8
        for (int d = 0; d < D; d++) a += spool[d] * ow[d * 2 + t];
        out[b * 2 + t] = a;
    }
}

// ---------------- launch ----------------
extern "C" void kernel_launch(void* const* d_in, const int* in_sizes, int n_in,
                              void* d_out, int out_size) {
    const float* features  = (const float*)d_in[0];
    const int*   src       = (const int*)  d_in[1];
    const int*   dst       = (const int*)  d_in[2];
    const int*   url       = (const int*)  d_in[3];
    const float* gat_fc_w  = (const float*)d_in[4];
    const float* attn_l    = (const float*)d_in[5];
    const float* attn_r    = (const float*)d_in[6];
    const float* gat_res_w = (const float*)d_in[7];
    const float* gat_bias  = (const float*)d_in[8];
    const float* ln_g      = (const float*)d_in[9];
    const float* ln_b      = (const float*)d_in[10];
    const float* wq        = (const float*)d_in[11];
    const float* wk        = (const float*)d_in[12];
    const float* wv        = (const float*)d_in[13];
    const float* fc_w      = (const float*)d_in[14];
    const float* fc_b      = (const float*)d_in[15];
    const float* mha_ln_g  = (const float*)d_in[16];
    const float* mha_ln_b  = (const float*)d_in[17];
    const float* out_w     = (const float*)d_in[18];
    const float* out_b     = (const float*)d_in[19];
    float* out = (float*)d_out;

    k_initfold<<<212, 256>>>(gat_fc_w, attn_l, attn_r, wq, wk, wv, fc_w);
    k_scatter<<<4, 256>>>(url);
    k_filter<<<(E_EDGES / 4 + 255) / 256, 256>>>(src, dst);
    k_gat<<<BSZ, 256>>>(features, url);
    k_rst_res<<<dim3(8, BSZ / 32), 256>>>(features, gat_res_w, gat_fc_w, url,
                                          gat_bias, ln_g, ln_b);
    k_yz<<<dim3(16, 128), 256>>>();
    k_attn_final<<<BSZ, 256>>>(fc_b, mha_ln_g, mha_ln_b, out_w, out_b, out);
}